// round 13
// baseline (speedup 1.0000x reference)
#include <cuda_runtime.h>
#include <cuda_bf16.h>
#include <cstdint>

#define NUM_EXPERT 8
#define IN_FEAT 1024
#define OUT_FEAT 4096
#define N_TOKENS 4096

#define BM 256
#define BN 128
#define BKF 32                    // K floats per stage (= 128 bytes per row)
#define NCHUNK (IN_FEAT / BKF)    // 32
#define NSTAGE 3
#define NTHREADS 256              // 8 warps @ 64x64 (4m x 2n)

#define A_STAGE_BYTES (BM * 128)              // 32768
#define B_STAGE_BYTES (BN * 128)              // 16384
#define STAGE_BYTES   (A_STAGE_BYTES + B_STAGE_BYTES)   // 49152
#define SMEM_TOTAL    (NSTAGE * STAGE_BYTES)            // 147456

// Scratch (no allocations allowed).
__device__ int g_perm[N_TOKENS];
__device__ int g_cnt[NUM_EXPERT];
__device__ int g_off[NUM_EXPERT];
// Pre-permuted, tf32-rounded activations (sorted by expert). Padded by BM rows:
// the last tile of an expert may read up to BM-1 rows past off+cnt (discarded).
__device__ float g_a[(size_t)(N_TOKENS + BM) * IN_FEAT];

// ---------------------------------------------------------------------------
// Kernel 1: counting sort of tokens by expert (single block).
// ---------------------------------------------------------------------------
__global__ void build_perm_kernel(const int* __restrict__ gate) {
    __shared__ int s_cnt[NUM_EXPERT];
    __shared__ int s_base[NUM_EXPERT];
    int t = threadIdx.x;
    if (t < NUM_EXPERT) s_cnt[t] = 0;
    __syncthreads();
    for (int i = t; i < N_TOKENS; i += blockDim.x)
        atomicAdd(&s_cnt[gate[i]], 1);
    __syncthreads();
    if (t == 0) {
        int acc = 0;
        for (int e = 0; e < NUM_EXPERT; e++) {
            s_base[e] = acc;
            g_off[e] = acc;
            g_cnt[e] = s_cnt[e];
            acc += s_cnt[e];
        }
    }
    __syncthreads();
    for (int i = t; i < N_TOKENS; i += blockDim.x) {
        int e = gate[i];
        int pos = atomicAdd(&s_base[e], 1);
        g_perm[pos] = i;
    }
}

// ---------------------------------------------------------------------------
// Kernel 1b: gather inp rows through perm into g_a, rounding to tf32 (rna).
// ---------------------------------------------------------------------------
__global__ __launch_bounds__(256) void gather_cvt_kernel(const float* __restrict__ inp) {
    const int p   = blockIdx.x;                 // sorted position
    const int row = g_perm[p];
    const float4* src = (const float4*)(inp + (size_t)row * IN_FEAT);
    float4* dst       = (float4*)(g_a + (size_t)p * IN_FEAT);
    float4 v = src[threadIdx.x];
    uint32_t x0, x1, x2, x3;
    asm("cvt.rna.tf32.f32 %0, %1;" : "=r"(x0) : "f"(v.x));
    asm("cvt.rna.tf32.f32 %0, %1;" : "=r"(x1) : "f"(v.y));
    asm("cvt.rna.tf32.f32 %0, %1;" : "=r"(x2) : "f"(v.z));
    asm("cvt.rna.tf32.f32 %0, %1;" : "=r"(x3) : "f"(v.w));
    float4 o;
    o.x = __uint_as_float(x0); o.y = __uint_as_float(x1);
    o.z = __uint_as_float(x2); o.w = __uint_as_float(x3);
    dst[threadIdx.x] = o;
}

// ---------------------------------------------------------------------------
// helpers
// ---------------------------------------------------------------------------
__device__ __forceinline__ uint32_t smem_u32(const void* p) {
    uint32_t a;
    asm("{ .reg .u64 t; cvta.to.shared.u64 t, %1; cvt.u32.u64 %0, t; }" : "=r"(a) : "l"(p));
    return a;
}
__device__ __forceinline__ void cp16(uint32_t dst, const void* src) {
    asm volatile("cp.async.cg.shared.global [%0], [%1], 16;"
                 :: "r"(dst), "l"(src) : "memory");
}
__device__ __forceinline__ void cp_commit() {
    asm volatile("cp.async.commit_group;" ::: "memory");
}
__device__ __forceinline__ void cp_wait1() {
    asm volatile("cp.async.wait_group 1;" ::: "memory");
}
__device__ __forceinline__ void ldsm4(uint32_t& r0, uint32_t& r1, uint32_t& r2, uint32_t& r3,
                                      uint32_t addr) {
    asm volatile("ldmatrix.sync.aligned.m8n8.x4.shared.b16 {%0,%1,%2,%3}, [%4];"
                 : "=r"(r0), "=r"(r1), "=r"(r2), "=r"(r3) : "r"(addr));
}
__device__ __forceinline__ void mma_tf32(float& c0, float& c1, float& c2, float& c3,
                                         uint32_t a0, uint32_t a1, uint32_t a2, uint32_t a3,
                                         uint32_t b0, uint32_t b1) {
    asm volatile(
        "mma.sync.aligned.m16n8k8.row.col.f32.tf32.tf32.f32 "
        "{%0,%1,%2,%3}, {%4,%5,%6,%7}, {%8,%9}, {%0,%1,%2,%3};"
        : "+f"(c0), "+f"(c1), "+f"(c2), "+f"(c3)
        : "r"(a0), "r"(a1), "r"(a2), "r"(a3), "r"(b0), "r"(b1));
}
__device__ __forceinline__ void stg_cs_v2(float* p, float x, float y) {
    asm volatile("st.global.cs.v2.f32 [%0], {%1, %2};"
                 :: "l"(p), "f"(x), "f"(y) : "memory");
}

// ---------------------------------------------------------------------------
// Kernel 2: tf32 mma.sync grouped GEMM. 256x128 CTA tile (halves B-side L2
// traffic vs 128x128), 8 warps @ 64x64 (4m x 2n), 256 threads, 3-stage
// cp.async pipeline, 1 CTA/SM.
//   C[m, n] = sum_k g_a[off + m, k] * weight[e, n, k]
// A pre-rounded (rna) in g_a; B raw f32 bits (HW tf32 truncation).
// ---------------------------------------------------------------------------
__global__ __launch_bounds__(NTHREADS, 1) void moe_gemm_mma_kernel(
    const float* __restrict__ weight,
    float* __restrict__ out)
{
    const int e   = blockIdx.z;
    const int cnt = g_cnt[e];
    const int mt  = blockIdx.y;
    if (mt * BM >= cnt) return;
    const int nt  = blockIdx.x;
    const int off = g_off[e];

    extern __shared__ char smem[];
    const uint32_t sbase = smem_u32(smem);

    const int tid  = threadIdx.x;
    const int wid  = tid >> 5;
    const int lane = tid & 31;
    const int wm   = (wid & 3) * 64;   // warp m-offset (4 warps in m)
    const int wn   = (wid >> 2) * 64;  // warp n-offset (2 warps in n)

    // ---- loader precompute: 8 A + 4 B cp16 per thread per stage ----
    const int lc  = tid & 7;           // 16B column (0..7)
    const int lr  = tid >> 3;          // base row (0..31)
    const uint32_t swc = (uint32_t)((lc ^ (lr & 7)) << 4);   // (lr+32j)&7 == lr&7
    uint32_t a_offs[8], b_offs[4];
    const float* a_src[8];
    const float* b_src[4];
    const float* wB = weight + (size_t)e * OUT_FEAT * IN_FEAT
                             + (size_t)(nt * BN) * IN_FEAT;
    #pragma unroll
    for (int j = 0; j < 8; j++) {
        int r = lr + 32 * j;
        a_offs[j] = (uint32_t)(r * 128) + swc;
        a_src[j]  = g_a + (size_t)(off + mt * BM + r) * IN_FEAT + lc * 4;
    }
    #pragma unroll
    for (int j = 0; j < 4; j++) {
        int r = lr + 32 * j;
        b_offs[j] = (uint32_t)(r * 128) + swc;
        b_src[j]  = wB + (size_t)r * IN_FEAT + lc * 4;
    }

    // ---- prologue: fill stages 0..1 with chunks 0..1 ----
    #pragma unroll
    for (int i = 0; i < NSTAGE - 1; i++) {
        uint32_t sA = sbase + i * STAGE_BYTES;
        uint32_t sB = sA + A_STAGE_BYTES;
        #pragma unroll
        for (int j = 0; j < 8; j++) cp16(sA + a_offs[j], a_src[j] + i * BKF);
        #pragma unroll
        for (int j = 0; j < 4; j++) cp16(sB + b_offs[j], b_src[j] + i * BKF);
        cp_commit();
    }

    // ---- fragment addressing (tile-invariant) ----
    const int asel = lane & 7;
    const int aRowBase = wm + (lane & 7) + ((lane >> 3) & 1) * 8;
    const int aCLane   = (lane >> 4) & 1;
    const int bRowBase = wn + (lane & 7) + ((lane >> 4) & 1) * 8;
    const int bCLane   = (lane >> 3) & 1;

    uint32_t aRowOff[4], bRowOff[4];
    #pragma unroll
    for (int mi = 0; mi < 4; mi++) aRowOff[mi] = (uint32_t)((aRowBase + mi * 16) * 128);
    #pragma unroll
    for (int p = 0; p < 4; p++)    bRowOff[p]  = (uint32_t)((bRowBase + p * 16) * 128);

    uint32_t cA[4], cB[4];
    #pragma unroll
    for (int ks = 0; ks < 4; ks++) {
        cA[ks] = (uint32_t)((((2 * ks + aCLane) ^ asel)) << 4);
        cB[ks] = (uint32_t)((((2 * ks + bCLane) ^ asel)) << 4);
    }

    float acc[4][8][4];
    #pragma unroll
    for (int mi = 0; mi < 4; mi++)
        #pragma unroll
        for (int ni = 0; ni < 8; ni++)
            #pragma unroll
            for (int r = 0; r < 4; r++)
                acc[mi][ni][r] = 0.0f;

    // ---- main loop over 32 K-chunks ----
    for (int i = 0; i < NCHUNK; i++) {
        cp_wait1();
        __syncthreads();

        int nx = i + NSTAGE - 1;
        if (nx < NCHUNK) {
            uint32_t sA = sbase + (nx % NSTAGE) * STAGE_BYTES;
            uint32_t sB = sA + A_STAGE_BYTES;
            #pragma unroll
            for (int j = 0; j < 8; j++) cp16(sA + a_offs[j], a_src[j] + nx * BKF);
            #pragma unroll
            for (int j = 0; j < 4; j++) cp16(sB + b_offs[j], b_src[j] + nx * BKF);
        }
        cp_commit();

        const uint32_t sA = sbase + (i % NSTAGE) * STAGE_BYTES;
        const uint32_t sB = sA + A_STAGE_BYTES;

        #pragma unroll
        for (int ks = 0; ks < 4; ks++) {
            uint32_t a[4][4], b[8][2];
            #pragma unroll
            for (int mi = 0; mi < 4; mi++)
                ldsm4(a[mi][0], a[mi][1], a[mi][2], a[mi][3], sA + aRowOff[mi] + cA[ks]);
            #pragma unroll
            for (int p = 0; p < 4; p++) {
                uint32_t t0, t1, t2, t3;
                ldsm4(t0, t1, t2, t3, sB + bRowOff[p] + cB[ks]);
                b[2 * p][0] = t0; b[2 * p][1] = t1;
                b[2 * p + 1][0] = t2; b[2 * p + 1][1] = t3;
            }
            #pragma unroll
            for (int mi = 0; mi < 4; mi++)
                #pragma unroll
                for (int ni = 0; ni < 8; ni++)
                    mma_tf32(acc[mi][ni][0], acc[mi][ni][1], acc[mi][ni][2], acc[mi][ni][3],
                             a[mi][0], a[mi][1], a[mi][2], a[mi][3],
                             b[ni][0], b[ni][1]);
        }
    }

    // ---- epilogue: scatter valid rows back through perm (streaming stores) ----
    const int q  = lane >> 2;
    const int cc = 2 * (lane & 3);
    #pragma unroll
    for (int mi = 0; mi < 4; mi++) {
        #pragma unroll
        for (int half = 0; half < 2; half++) {
            const int r = wm + mi * 16 + q + half * 8;
            const int m = mt * BM + r;
            if (m < cnt) {
                float* orow = out + (size_t)g_perm[off + m] * OUT_FEAT
                                  + nt * BN + wn + cc;
                #pragma unroll
                for (int ni = 0; ni < 8; ni++)
                    stg_cs_v2(orow + ni * 8,
                              acc[mi][ni][half * 2], acc[mi][ni][half * 2 + 1]);
            }
        }
    }
}

extern "C" void kernel_launch(void* const* d_in, const int* in_sizes, int n_in,
                              void* d_out, int out_size) {
    const float* inp    = (const float*)d_in[0];   // [N_TOKENS, IN_FEAT] f32
    const int*   gate   = (const int*)d_in[1];     // [N_TOKENS] i32
    const float* weight = (const float*)d_in[2];   // [NUM_EXPERT, OUT_FEAT, IN_FEAT] f32
    float* out = (float*)d_out;                    // [N_TOKENS, OUT_FEAT] f32

    cudaFuncSetAttribute(moe_gemm_mma_kernel,
                         cudaFuncAttributeMaxDynamicSharedMemorySize, SMEM_TOTAL);

    build_perm_kernel<<<1, 256>>>(gate);
    gather_cvt_kernel<<<N_TOKENS, 256>>>(inp);

    dim3 grid(OUT_FEAT / BN, N_TOKENS / BM, NUM_EXPERT);
    moe_gemm_mma_kernel<<<grid, NTHREADS, SMEM_TOTAL>>>(weight, out);
}

// round 14
// speedup vs baseline: 1.4097x; 1.4097x over previous
#include <cuda_runtime.h>
#include <cuda_bf16.h>
#include <cstdint>

#define NUM_EXPERT 8
#define IN_FEAT 1024
#define OUT_FEAT 4096
#define N_TOKENS 4096

#define BM 128
#define BN 128
#define BKF 32                    // K floats per stage (= 128 bytes per row)
#define NCHUNK (IN_FEAT / BKF)    // 32
#define NSTAGE 3
#define NTHREADS 128              // 4 warps, each owning a 64x64 sub-tile

#define A_STAGE_BYTES (BM * 128)              // 16384
#define STAGE_BYTES   (2 * BM * 128)          // 32768 (A then B)
#define SMEM_TOTAL    (NSTAGE * STAGE_BYTES)  // 98304

// Scratch (no allocations allowed).
// g_perm padded by BM entries (filled with 0) so the last tile of an expert
// can load rows unconditionally; results for rows >= cnt are discarded.
__device__ int g_perm[N_TOKENS + BM];
__device__ int g_cnt[NUM_EXPERT];
__device__ int g_off[NUM_EXPERT];

// ---------------------------------------------------------------------------
// Kernel 1: counting sort of tokens by expert (single block).
// ---------------------------------------------------------------------------
__global__ void build_perm_kernel(const int* __restrict__ gate) {
    __shared__ int s_cnt[NUM_EXPERT];
    __shared__ int s_base[NUM_EXPERT];
    int t = threadIdx.x;
    if (t < NUM_EXPERT) s_cnt[t] = 0;
    __syncthreads();
    for (int i = t; i < N_TOKENS; i += blockDim.x)
        atomicAdd(&s_cnt[gate[i]], 1);
    __syncthreads();
    if (t == 0) {
        int acc = 0;
        for (int e = 0; e < NUM_EXPERT; e++) {
            s_base[e] = acc;
            g_off[e] = acc;
            g_cnt[e] = s_cnt[e];
            acc += s_cnt[e];
        }
    }
    __syncthreads();
    for (int i = t; i < N_TOKENS; i += blockDim.x) {
        int e = gate[i];
        int pos = atomicAdd(&s_base[e], 1);
        g_perm[pos] = i;
    }
    // pad tail so GEMM loaders never index past valid perm entries
    if (t < BM) g_perm[N_TOKENS + t] = 0;
}

// ---------------------------------------------------------------------------
// helpers
// ---------------------------------------------------------------------------
__device__ __forceinline__ uint32_t smem_u32(const void* p) {
    uint32_t a;
    asm("{ .reg .u64 t; cvta.to.shared.u64 t, %1; cvt.u32.u64 %0, t; }" : "=r"(a) : "l"(p));
    return a;
}
__device__ __forceinline__ void cp16(uint32_t dst, const void* src) {
    asm volatile("cp.async.cg.shared.global [%0], [%1], 16;"
                 :: "r"(dst), "l"(src) : "memory");
}
__device__ __forceinline__ void cp_commit() {
    asm volatile("cp.async.commit_group;" ::: "memory");
}
__device__ __forceinline__ void cp_wait1() {
    asm volatile("cp.async.wait_group 1;" ::: "memory");
}
__device__ __forceinline__ void ldsm4(uint32_t& r0, uint32_t& r1, uint32_t& r2, uint32_t& r3,
                                      uint32_t addr) {
    asm volatile("ldmatrix.sync.aligned.m8n8.x4.shared.b16 {%0,%1,%2,%3}, [%4];"
                 : "=r"(r0), "=r"(r1), "=r"(r2), "=r"(r3) : "r"(addr));
}
__device__ __forceinline__ void mma_tf32(float& c0, float& c1, float& c2, float& c3,
                                         uint32_t a0, uint32_t a1, uint32_t a2, uint32_t a3,
                                         uint32_t b0, uint32_t b1) {
    asm volatile(
        "mma.sync.aligned.m16n8k8.row.col.f32.tf32.tf32.f32 "
        "{%0,%1,%2,%3}, {%4,%5,%6,%7}, {%8,%9}, {%0,%1,%2,%3};"
        : "+f"(c0), "+f"(c1), "+f"(c2), "+f"(c3)
        : "r"(a0), "r"(a1), "r"(a2), "r"(a3), "r"(b0), "r"(b1));
}
__device__ __forceinline__ void stg_cs_v2(float* p, float x, float y) {
    asm volatile("st.global.cs.v2.f32 [%0], {%1, %2};"
                 :: "l"(p), "f"(x), "f"(y) : "memory");
}

// ---------------------------------------------------------------------------
// Kernel 2: tf32 mma.sync grouped GEMM. 128x128 CTA tile, 4 warps @ 64x64,
// 128 threads, 3-stage cp.async pipeline, 2 CTAs/SM.
//   C[m, n] = sum_k inp[perm[off+m], k] * weight[e, n, k]
// Both A and B fed as raw f32 bits; HW tf32 truncation (measured-model
// rel_err ~6e-4 < 1e-3). No pre-pass gather, no cvt anywhere.
// ---------------------------------------------------------------------------
__global__ __launch_bounds__(NTHREADS, 2) void moe_gemm_mma_kernel(
    const float* __restrict__ inp,
    const float* __restrict__ weight,
    float* __restrict__ out)
{
    const int e   = blockIdx.z;
    const int cnt = g_cnt[e];
    const int mt  = blockIdx.y;
    if (mt * BM >= cnt) return;
    const int nt  = blockIdx.x;
    const int off = g_off[e];

    extern __shared__ char smem[];
    const uint32_t sbase = smem_u32(smem);

    const int tid  = threadIdx.x;
    const int wid  = tid >> 5;
    const int lane = tid & 31;
    const int wm   = (wid & 1) * 64;   // warp m-offset (2 warps in m)
    const int wn   = (wid >> 1) * 64;  // warp n-offset (2 warps in n)

    // ---- loader precompute: 8 A + 8 B cp16 per thread per stage ----
    const int lc  = tid & 7;           // 16B column (0..7)
    const int lr  = tid >> 3;          // base row (0..15)
    const uint32_t swc = (uint32_t)((lc ^ (lr & 7)) << 4);   // (lr+16j)&7 == lr&7
    uint32_t d_off[8];
    const float* a_src[8];
    const float* b_src[8];
    const float* wB = weight + (size_t)e * OUT_FEAT * IN_FEAT
                             + (size_t)(nt * BN) * IN_FEAT;
    #pragma unroll
    for (int j = 0; j < 8; j++) {
        int r = lr + 16 * j;
        d_off[j] = (uint32_t)(r * 128) + swc;
        // direct gather through padded perm (rows >= cnt map to token 0,
        // computed and discarded by the epilogue mask)
        a_src[j] = inp + (size_t)g_perm[off + mt * BM + r] * IN_FEAT + lc * 4;
        b_src[j] = wB + (size_t)r * IN_FEAT + lc * 4;
    }

    // ---- prologue: fill stages 0..1 with chunks 0..1 ----
    #pragma unroll
    for (int i = 0; i < NSTAGE - 1; i++) {
        uint32_t sA = sbase + i * STAGE_BYTES;
        uint32_t sB = sA + A_STAGE_BYTES;
        #pragma unroll
        for (int j = 0; j < 8; j++) {
            cp16(sA + d_off[j], a_src[j] + i * BKF);
            cp16(sB + d_off[j], b_src[j] + i * BKF);
        }
        cp_commit();
    }

    // ---- fragment addressing (tile-invariant) ----
    const int asel = lane & 7;
    const int aRowBase = wm + (lane & 7) + ((lane >> 3) & 1) * 8;
    const int aCLane   = (lane >> 4) & 1;
    const int bRowBase = wn + (lane & 7) + ((lane >> 4) & 1) * 8;
    const int bCLane   = (lane >> 3) & 1;

    uint32_t aRowOff[4], bRowOff[4];
    #pragma unroll
    for (int mi = 0; mi < 4; mi++) aRowOff[mi] = (uint32_t)((aRowBase + mi * 16) * 128);
    #pragma unroll
    for (int p = 0; p < 4; p++)    bRowOff[p]  = (uint32_t)((bRowBase + p * 16) * 128);

    uint32_t cA[4], cB[4];
    #pragma unroll
    for (int ks = 0; ks < 4; ks++) {
        cA[ks] = (uint32_t)((((2 * ks + aCLane) ^ asel)) << 4);
        cB[ks] = (uint32_t)((((2 * ks + bCLane) ^ asel)) << 4);
    }

    float acc[4][8][4];
    #pragma unroll
    for (int mi = 0; mi < 4; mi++)
        #pragma unroll
        for (int ni = 0; ni < 8; ni++)
            #pragma unroll
            for (int r = 0; r < 4; r++)
                acc[mi][ni][r] = 0.0f;

    // ---- main loop over 32 K-chunks ----
    for (int i = 0; i < NCHUNK; i++) {
        cp_wait1();
        __syncthreads();

        int nx = i + NSTAGE - 1;
        if (nx < NCHUNK) {
            uint32_t sA = sbase + (nx % NSTAGE) * STAGE_BYTES;
            uint32_t sB = sA + A_STAGE_BYTES;
            #pragma unroll
            for (int j = 0; j < 8; j++) {
                cp16(sA + d_off[j], a_src[j] + nx * BKF);
                cp16(sB + d_off[j], b_src[j] + nx * BKF);
            }
        }
        cp_commit();

        const uint32_t sA = sbase + (i % NSTAGE) * STAGE_BYTES;
        const uint32_t sB = sA + A_STAGE_BYTES;

        #pragma unroll
        for (int ks = 0; ks < 4; ks++) {
            uint32_t a[4][4], b[8][2];
            #pragma unroll
            for (int mi = 0; mi < 4; mi++)
                ldsm4(a[mi][0], a[mi][1], a[mi][2], a[mi][3], sA + aRowOff[mi] + cA[ks]);
            #pragma unroll
            for (int p = 0; p < 4; p++) {
                uint32_t t0, t1, t2, t3;
                ldsm4(t0, t1, t2, t3, sB + bRowOff[p] + cB[ks]);
                b[2 * p][0] = t0; b[2 * p][1] = t1;
                b[2 * p + 1][0] = t2; b[2 * p + 1][1] = t3;
            }
            #pragma unroll
            for (int mi = 0; mi < 4; mi++)
                #pragma unroll
                for (int ni = 0; ni < 8; ni++)
                    mma_tf32(acc[mi][ni][0], acc[mi][ni][1], acc[mi][ni][2], acc[mi][ni][3],
                             a[mi][0], a[mi][1], a[mi][2], a[mi][3],
                             b[ni][0], b[ni][1]);
        }
    }

    // ---- epilogue: scatter valid rows back through perm (streaming stores) ----
    const int q  = lane >> 2;
    const int cc = 2 * (lane & 3);
    #pragma unroll
    for (int mi = 0; mi < 4; mi++) {
        #pragma unroll
        for (int half = 0; half < 2; half++) {
            const int r = wm + mi * 16 + q + half * 8;
            const int m = mt * BM + r;
            if (m < cnt) {
                float* orow = out + (size_t)g_perm[off + m] * OUT_FEAT
                                  + nt * BN + wn + cc;
                #pragma unroll
                for (int ni = 0; ni < 8; ni++)
                    stg_cs_v2(orow + ni * 8,
                              acc[mi][ni][half * 2], acc[mi][ni][half * 2 + 1]);
            }
        }
    }
}

extern "C" void kernel_launch(void* const* d_in, const int* in_sizes, int n_in,
                              void* d_out, int out_size) {
    const float* inp    = (const float*)d_in[0];   // [N_TOKENS, IN_FEAT] f32
    const int*   gate   = (const int*)d_in[1];     // [N_TOKENS] i32
    const float* weight = (const float*)d_in[2];   // [NUM_EXPERT, OUT_FEAT, IN_FEAT] f32
    float* out = (float*)d_out;                    // [N_TOKENS, OUT_FEAT] f32

    cudaFuncSetAttribute(moe_gemm_mma_kernel,
                         cudaFuncAttributeMaxDynamicSharedMemorySize, SMEM_TOTAL);

    build_perm_kernel<<<1, 256>>>(gate);

    dim3 grid(OUT_FEAT / BN, N_TOKENS / BM, NUM_EXPERT);
    moe_gemm_mma_kernel<<<grid, NTHREADS, SMEM_TOTAL>>>(inp, weight, out);
}

// round 15
// speedup vs baseline: 1.4282x; 1.0131x over previous
#include <cuda_runtime.h>
#include <cuda_bf16.h>
#include <cstdint>

#define NUM_EXPERT 8
#define IN_FEAT 1024
#define OUT_FEAT 4096
#define N_TOKENS 4096

#define BM 128
#define BN 128
#define BKF 32                    // K floats per stage (= 128 bytes per row)
#define NCHUNK (IN_FEAT / BKF)    // 32
#define NSTAGE 3
#define NTHREADS 128              // 4 warps, each owning a 64x64 sub-tile
#define NT_TILES (OUT_FEAT / BN)  // 32
#define GRID_P 304                // 2 CTAs/SM x 152 SMs

#define A_STAGE_BYTES (BM * 128)              // 16384
#define STAGE_BYTES   (2 * BM * 128)          // 32768 (A then B)
#define SMEM_TOTAL    (NSTAGE * STAGE_BYTES)  // 98304

// Scratch (no allocations allowed).
// g_perm padded by BM zeros so tile loaders never read past valid entries.
__device__ int g_perm[N_TOKENS + BM];
__device__ int g_cnt[NUM_EXPERT];
__device__ int g_off[NUM_EXPERT];
__device__ int g_tile_e[64];
__device__ int g_tile_mt[64];
__device__ int g_nwork;          // total work items = nrec * 32

// ---------------------------------------------------------------------------
// Kernel 1: counting sort by expert + flat tile worklist (single block).
// ---------------------------------------------------------------------------
__global__ void build_perm_kernel(const int* __restrict__ gate) {
    __shared__ int s_cnt[NUM_EXPERT];
    __shared__ int s_base[NUM_EXPERT];
    int t = threadIdx.x;
    if (t < NUM_EXPERT) s_cnt[t] = 0;
    __syncthreads();
    for (int i = t; i < N_TOKENS; i += blockDim.x)
        atomicAdd(&s_cnt[gate[i]], 1);
    __syncthreads();
    if (t == 0) {
        int acc = 0, nrec = 0;
        for (int e = 0; e < NUM_EXPERT; e++) {
            s_base[e] = acc;
            g_off[e] = acc;
            g_cnt[e] = s_cnt[e];
            int mtiles = (s_cnt[e] + BM - 1) / BM;
            for (int mt = 0; mt < mtiles; mt++) {
                g_tile_e[nrec] = e;
                g_tile_mt[nrec] = mt;
                nrec++;
            }
            acc += s_cnt[e];
        }
        g_nwork = nrec * NT_TILES;
    }
    __syncthreads();
    for (int i = t; i < N_TOKENS; i += blockDim.x) {
        int e = gate[i];
        int pos = atomicAdd(&s_base[e], 1);
        g_perm[pos] = i;
    }
    if (t < BM) g_perm[N_TOKENS + t] = 0;
}

// ---------------------------------------------------------------------------
// helpers
// ---------------------------------------------------------------------------
__device__ __forceinline__ uint32_t smem_u32(const void* p) {
    uint32_t a;
    asm("{ .reg .u64 t; cvta.to.shared.u64 t, %1; cvt.u32.u64 %0, t; }" : "=r"(a) : "l"(p));
    return a;
}
__device__ __forceinline__ void cp16(uint32_t dst, const void* src) {
    asm volatile("cp.async.cg.shared.global [%0], [%1], 16;"
                 :: "r"(dst), "l"(src) : "memory");
}
__device__ __forceinline__ void cp_commit() {
    asm volatile("cp.async.commit_group;" ::: "memory");
}
__device__ __forceinline__ void cp_wait1() {
    asm volatile("cp.async.wait_group 1;" ::: "memory");
}
__device__ __forceinline__ void ldsm4(uint32_t& r0, uint32_t& r1, uint32_t& r2, uint32_t& r3,
                                      uint32_t addr) {
    asm volatile("ldmatrix.sync.aligned.m8n8.x4.shared.b16 {%0,%1,%2,%3}, [%4];"
                 : "=r"(r0), "=r"(r1), "=r"(r2), "=r"(r3) : "r"(addr));
}
__device__ __forceinline__ void mma_tf32(float& c0, float& c1, float& c2, float& c3,
                                         uint32_t a0, uint32_t a1, uint32_t a2, uint32_t a3,
                                         uint32_t b0, uint32_t b1) {
    asm volatile(
        "mma.sync.aligned.m16n8k8.row.col.f32.tf32.tf32.f32 "
        "{%0,%1,%2,%3}, {%4,%5,%6,%7}, {%8,%9}, {%0,%1,%2,%3};"
        : "+f"(c0), "+f"(c1), "+f"(c2), "+f"(c3)
        : "r"(a0), "r"(a1), "r"(a2), "r"(a3), "r"(b0), "r"(b1));
}
__device__ __forceinline__ void stg_cs_v2(float* p, float x, float y) {
    asm volatile("st.global.cs.v2.f32 [%0], {%1, %2};"
                 :: "l"(p), "f"(x), "f"(y) : "memory");
}

// ---------------------------------------------------------------------------
// Kernel 2: flattened persistent tf32 GEMM. 128x128 tile, 4 warps @ 64x64,
// 128 threads, 2 CTAs/SM, STATIC tile stride (no atomics). The cp.async
// stream never drains: at chunks 30/31 the prefetch cursor crosses into the
// next tile's chunks 0/1, so the register-only epilogue overlaps the next
// tile's loads and every tile starts with a hot pipeline.
//   C[m, n] = sum_k inp[perm[off+m], k] * weight[e, n, k]
// A and B fed as raw f32 bits (HW tf32 truncation; rel_err ~7.7e-4 < 1e-3).
// ---------------------------------------------------------------------------
__global__ __launch_bounds__(NTHREADS, 2) void moe_gemm_mma_kernel(
    const float* __restrict__ inp,
    const float* __restrict__ weight,
    float* __restrict__ out)
{
    extern __shared__ char smem[];
    const uint32_t sbase = smem_u32(smem);

    const int cta   = blockIdx.x;
    const int nwork = g_nwork;

    const int tid  = threadIdx.x;
    const int wid  = tid >> 5;
    const int lane = tid & 31;
    const int wm   = (wid & 1) * 64;
    const int wn   = (wid >> 1) * 64;

    // ---- tile-invariant loader constants ----
    const int lc  = tid & 7;
    const int lr  = tid >> 3;
    const uint32_t swc = (uint32_t)((lc ^ (lr & 7)) << 4);
    uint32_t d_off[8];
    #pragma unroll
    for (int j = 0; j < 8; j++)
        d_off[j] = (uint32_t)((lr + 16 * j) * 128) + swc;

    // ---- tile-invariant fragment addressing ----
    const int asel = lane & 7;
    const int aRowBase = wm + (lane & 7) + ((lane >> 3) & 1) * 8;
    const int aCLane   = (lane >> 4) & 1;
    const int bRowBase = wn + (lane & 7) + ((lane >> 4) & 1) * 8;
    const int bCLane   = (lane >> 3) & 1;
    uint32_t aRowOff[4], bRowOff[4];
    #pragma unroll
    for (int mi = 0; mi < 4; mi++) aRowOff[mi] = (uint32_t)((aRowBase + mi * 16) * 128);
    #pragma unroll
    for (int p = 0; p < 4; p++)    bRowOff[p]  = (uint32_t)((bRowBase + p * 16) * 128);
    uint32_t cA[4], cB[4];
    #pragma unroll
    for (int ks = 0; ks < 4; ks++) {
        cA[ks] = (uint32_t)((((2 * ks + aCLane) ^ asel)) << 4);
        cB[ks] = (uint32_t)((((2 * ks + bCLane) ^ asel)) << 4);
    }

    // ---- loader pointers (updated per tile; swapped mid-mainloop at i==30) ----
    const float* a_src[8];
    const float* b_src[8];

#define SETUP_LOADER_PTRS(W) do {                                              \
        int _rec = (W) >> 5;                                                   \
        int _nt  = (W) & (NT_TILES - 1);                                       \
        int _e   = g_tile_e[_rec];                                             \
        int _mt  = g_tile_mt[_rec];                                            \
        int _off = g_off[_e];                                                  \
        const float* _wB = weight + (size_t)_e * OUT_FEAT * IN_FEAT            \
                                  + (size_t)(_nt * BN) * IN_FEAT;              \
        _Pragma("unroll")                                                      \
        for (int _j = 0; _j < 8; _j++) {                                       \
            int _r = lr + 16 * _j;                                             \
            a_src[_j] = inp + (size_t)g_perm[_off + _mt * BM + _r] * IN_FEAT   \
                            + lc * 4;                                          \
            b_src[_j] = _wB + (size_t)_r * IN_FEAT + lc * 4;                   \
        }                                                                      \
    } while (0)

    int w = cta;                 // first tile (nwork >= 1024 > 304 always)
    SETUP_LOADER_PTRS(w);

    // ---- initial prologue: chunks 0,1 of first tile into stages 0,1 ----
    #pragma unroll
    for (int i = 0; i < NSTAGE - 1; i++) {
        uint32_t sA = sbase + i * STAGE_BYTES;
        uint32_t sB = sA + A_STAGE_BYTES;
        #pragma unroll
        for (int j = 0; j < 8; j++) {
            cp16(sA + d_off[j], a_src[j] + i * BKF);
            cp16(sB + d_off[j], b_src[j] + i * BKF);
        }
        cp_commit();
    }

    int srot = 0;                // stage of current tile's chunk 0

    while (w < nwork) {
        // epilogue metadata for THIS tile (loader ptrs get swapped at i==30)
        const int rec  = w >> 5;
        const int nt   = w & (NT_TILES - 1);
        const int e    = g_tile_e[rec];
        const int mt   = g_tile_mt[rec];
        const int cnt  = g_cnt[e];
        const int off  = g_off[e];
        const int wnxt = w + GRID_P;
        const bool have_next = wnxt < nwork;

        float acc[4][8][4];
        #pragma unroll
        for (int mi = 0; mi < 4; mi++)
            #pragma unroll
            for (int ni = 0; ni < 8; ni++)
                #pragma unroll
                for (int r = 0; r < 4; r++)
                    acc[mi][ni][r] = 0.0f;

        int sc = srot;                       // stage of chunk i
        for (int i = 0; i < NCHUNK; i++) {
            cp_wait1();
            __syncthreads();

            // load cursor: chunk i+2 (crosses into next tile's chunks 0,1)
            int sl = sc + 2; if (sl >= NSTAGE) sl -= NSTAGE;
            const int nx = i + 2;
            if (nx < NCHUNK) {
                uint32_t sA = sbase + sl * STAGE_BYTES;
                uint32_t sB = sA + A_STAGE_BYTES;
                #pragma unroll
                for (int j = 0; j < 8; j++) {
                    cp16(sA + d_off[j], a_src[j] + nx * BKF);
                    cp16(sB + d_off[j], b_src[j] + nx * BKF);
                }
            } else if (have_next) {
                if (nx == NCHUNK) SETUP_LOADER_PTRS(wnxt);   // swap once, at i==30
                const int c2 = nx - NCHUNK;                  // next tile chunk 0/1
                uint32_t sA = sbase + sl * STAGE_BYTES;
                uint32_t sB = sA + A_STAGE_BYTES;
                #pragma unroll
                for (int j = 0; j < 8; j++) {
                    cp16(sA + d_off[j], a_src[j] + c2 * BKF);
                    cp16(sB + d_off[j], b_src[j] + c2 * BKF);
                }
            }
            cp_commit();

            const uint32_t sA = sbase + sc * STAGE_BYTES;
            const uint32_t sB = sA + A_STAGE_BYTES;

            #pragma unroll
            for (int ks = 0; ks < 4; ks++) {
                uint32_t a[4][4], b[8][2];
                #pragma unroll
                for (int mi = 0; mi < 4; mi++)
                    ldsm4(a[mi][0], a[mi][1], a[mi][2], a[mi][3],
                          sA + aRowOff[mi] + cA[ks]);
                #pragma unroll
                for (int p = 0; p < 4; p++) {
                    uint32_t t0, t1, t2, t3;
                    ldsm4(t0, t1, t2, t3, sB + bRowOff[p] + cB[ks]);
                    b[2 * p][0] = t0; b[2 * p][1] = t1;
                    b[2 * p + 1][0] = t2; b[2 * p + 1][1] = t3;
                }
                #pragma unroll
                for (int mi = 0; mi < 4; mi++)
                    #pragma unroll
                    for (int ni = 0; ni < 8; ni++)
                        mma_tf32(acc[mi][ni][0], acc[mi][ni][1],
                                 acc[mi][ni][2], acc[mi][ni][3],
                                 a[mi][0], a[mi][1], a[mi][2], a[mi][3],
                                 b[ni][0], b[ni][1]);
            }

            sc = (sc + 1 == NSTAGE) ? 0 : sc + 1;
        }

        // ---- epilogue (registers only — overlaps next tile's in-flight loads)
        const int q  = lane >> 2;
        const int cc = 2 * (lane & 3);
        #pragma unroll
        for (int mi = 0; mi < 4; mi++) {
            #pragma unroll
            for (int half = 0; half < 2; half++) {
                const int r = wm + mi * 16 + q + half * 8;
                const int m = mt * BM + r;
                if (m < cnt) {
                    float* orow = out + (size_t)g_perm[off + m] * OUT_FEAT
                                      + nt * BN + wn + cc;
                    #pragma unroll
                    for (int ni = 0; ni < 8; ni++)
                        stg_cs_v2(orow + ni * 8,
                                  acc[mi][ni][half * 2], acc[mi][ni][half * 2 + 1]);
                }
            }
        }

        srot = sc;        // advanced 32 (== +2 mod 3): next tile chunk0's stage
        w = wnxt;
    }
#undef SETUP_LOADER_PTRS
}

extern "C" void kernel_launch(void* const* d_in, const int* in_sizes, int n_in,
                              void* d_out, int out_size) {
    const float* inp    = (const float*)d_in[0];   // [N_TOKENS, IN_FEAT] f32
    const int*   gate   = (const int*)d_in[1];     // [N_TOKENS] i32
    const float* weight = (const float*)d_in[2];   // [NUM_EXPERT, OUT_FEAT, IN_FEAT] f32
    float* out = (float*)d_out;                    // [N_TOKENS, OUT_FEAT] f32

    cudaFuncSetAttribute(moe_gemm_mma_kernel,
                         cudaFuncAttributeMaxDynamicSharedMemorySize, SMEM_TOTAL);

    build_perm_kernel<<<1, 256>>>(gate);
    moe_gemm_mma_kernel<<<GRID_P, NTHREADS, SMEM_TOTAL>>>(inp, weight, out);
}